// round 9
// baseline (speedup 1.0000x reference)
#include <cuda_runtime.h>
#include <cuda_bf16.h>
#include <cuda_fp16.h>
#include <cstdint>

#define NB    4
#define SQ    2048
#define PAST  2048
#define DIN   2048
#define DH    2048
#define DFF   8192
#define KVLEN (PAST + SQ)   // 4096

// ======================= device scratch (no allocation) ======================
__device__ float g_scores[(long long)NB * SQ * KVLEN];
__device__ __nv_bfloat16 g_xs [(long long)NB*SQ * 3*DIN];
__device__ __nv_bfloat16 g_qs [(long long)NB*SQ * 3*DH];
__device__ __nv_bfloat16 g_ks [(long long)NB*KVLEN * 3*DH];
__device__ __nv_bfloat16 g_wqs[(long long)DH * 3*DIN];
__device__ __nv_bfloat16 g_wks[(long long)DH * 3*DIN];
__device__ __half g_xh   [(long long)NB*SQ * DIN];
__device__ __half g_wvh  [(long long)DH * DIN];
__device__ __half g_wffh [(long long)DFF * DH];
__device__ __half g_wouth[(long long)DH * DFF];
__device__ __half g_vth  [(long long)NB * DH * KVLEN];
__device__ __half g_attnh[(long long)NB * SQ * KVLEN];
__device__ __half g_ctxh [(long long)NB * SQ * DH];
__device__ __half g_ffh  [(long long)NB * SQ * DFF];

// ======================= helpers =============================================
__device__ __forceinline__ uint32_t smem_u32(const void* p) {
    uint32_t a;
    asm("{ .reg .u64 t; cvta.to.shared.u64 t, %1; cvt.u32.u64 %0, t; }" : "=r"(a) : "l"(p));
    return a;
}
__device__ __forceinline__ void ldm4(uint32_t* f, uint32_t a) {
    asm volatile("ldmatrix.sync.aligned.m8n8.x4.shared.b16 {%0,%1,%2,%3}, [%4];"
                 : "=r"(f[0]), "=r"(f[1]), "=r"(f[2]), "=r"(f[3]) : "r"(a));
}
template<int DT>   // 0 = bf16, 1 = f16
__device__ __forceinline__ void mma_op(float* c, const uint32_t* a, uint32_t b0, uint32_t b1) {
    if (DT == 0)
        asm volatile("mma.sync.aligned.m16n8k16.row.col.f32.bf16.bf16.f32 "
                     "{%0,%1,%2,%3}, {%4,%5,%6,%7}, {%8,%9}, {%0,%1,%2,%3};"
                     : "+f"(c[0]), "+f"(c[1]), "+f"(c[2]), "+f"(c[3])
                     : "r"(a[0]), "r"(a[1]), "r"(a[2]), "r"(a[3]), "r"(b0), "r"(b1));
    else
        asm volatile("mma.sync.aligned.m16n8k16.row.col.f32.f16.f16.f32 "
                     "{%0,%1,%2,%3}, {%4,%5,%6,%7}, {%8,%9}, {%0,%1,%2,%3};"
                     : "+f"(c[0]), "+f"(c[1]), "+f"(c[2]), "+f"(c[3])
                     : "r"(a[0]), "r"(a[1]), "r"(a[2]), "r"(a[3]), "r"(b0), "r"(b1));
}
__device__ __forceinline__ unsigned short bf16bits(float f) {
    __nv_bfloat16 h = __float2bfloat16(f);
    return *reinterpret_cast<unsigned short*>(&h);
}
__device__ __forceinline__ float bf16val(unsigned short u) {
    __nv_bfloat16 h = *reinterpret_cast<__nv_bfloat16*>(&u);
    return __bfloat162float(h);
}
#define CP16(dst, src) asm volatile("cp.async.ca.shared.global [%0], [%1], 16;" :: "r"(dst), "l"(src) : "memory")
#define CP_COMMIT()    asm volatile("cp.async.commit_group;" ::: "memory")

// ======================= GEMM: C[M,N] = A[M,K]·B[N,K]^T =====================
// CTA 128x128, k-chunk 64. 128 threads = 4 warps (2M x 2N), warp tile 64x64.
// 3-stage cp.async pipeline, dynamic smem 3 x (16KB A + 16KB B) = 96KB -> 2 CTA/SM.
// Rows are 128B (64 fp16); swizzle: seg j (16B) of row r at ((j ^ (r&7)) << 4).
// Fragment double-buffering across the 4 k16-steps inside each chunk.
#define STG   32768
#define SMEM_GEMM (3 * STG)   // 98304

template<int DT>
__global__ void __launch_bounds__(128, 2)
gemm_tc(const uint16_t* __restrict__ A, const uint16_t* __restrict__ B,
        const float* __restrict__ bias, float* __restrict__ C,
        __nv_bfloat16* __restrict__ sA3, __half* __restrict__ sH,
        int N, long long Kp,
        long long aBatch, long long bBatch,
        int cBatchRows, int cRowOff)
{
    extern __shared__ __align__(16) uint8_t smem[];
    const uint32_t sb = smem_u32(smem);

    const int tid = threadIdx.x;
    const int wid = tid >> 5;
    const int lid = tid & 31;
    const long long bn0 = (long long)blockIdx.x * 128;
    const long long bm0 = (long long)blockIdx.y * 128;

    A += (long long)blockIdx.z * aBatch + bm0 * Kp;
    B += (long long)blockIdx.z * bBatch + bn0 * Kp;

    // loader: one 128B row per thread per operand
    const uint16_t* aG = A + (long long)tid * Kp;
    const uint16_t* bG = B + (long long)tid * Kp;
    const uint32_t rowOff = (uint32_t)tid * 128;
    const int rx = tid & 7;

    const int nT = (int)(Kp >> 6);

    auto ldStage = [&](int slot, int chunk) {
        const uint32_t ab = sb + slot * STG;
        const uint32_t bb = ab + 16384;
        const long long o = (long long)chunk * 64;
#pragma unroll
        for (int j = 0; j < 8; j++) CP16(ab + rowOff + (uint32_t)((j ^ rx) << 4), aG + o + j * 8);
#pragma unroll
        for (int j = 0; j < 8; j++) CP16(bb + rowOff + (uint32_t)((j ^ rx) << 4), bG + o + j * 8);
        CP_COMMIT();
    };
    ldStage(0, 0);
    ldStage(1, 1);

    // fragment addressing: warp (wm, wn), tile 64x64
    const int wm = wid & 1, wn = wid >> 1;
    const int l15 = lid & 15, h = lid >> 4;
    uint32_t aoff[4]; int axr[4];
#pragma unroll
    for (int i = 0; i < 4; i++) {
        const int r = wm * 64 + i * 16 + l15;
        aoff[i] = (uint32_t)r * 128; axr[i] = r & 7;
    }
    uint32_t boff[4]; int bxr[4];
#pragma unroll
    for (int g = 0; g < 4; g++) {
        const int r = wn * 64 + g * 16 + l15;
        boff[g] = (uint32_t)r * 128; bxr[g] = r & 7;
    }

    float acc[4][8][4];
#pragma unroll
    for (int i = 0; i < 4; i++)
#pragma unroll
        for (int j = 0; j < 8; j++)
#pragma unroll
            for (int k = 0; k < 4; k++) acc[i][j][k] = 0.f;

    for (int t = 0; t < nT; t++) {
        if (t + 1 < nT) asm volatile("cp.async.wait_group 1;" ::: "memory");
        else            asm volatile("cp.async.wait_group 0;" ::: "memory");
        __syncthreads();
        if (t + 2 < nT) ldStage((t + 2) % 3, t + 2);

        const uint32_t aB = sb + (t % 3) * STG;
        const uint32_t bB = aB + 16384;

        uint32_t af[2][4][4], bf[2][4][4];
        {   // k16-step 0 fragments
            const int jb = h;
#pragma unroll
            for (int i = 0; i < 4; i++)
                ldm4(af[0][i], aB + aoff[i] + (uint32_t)((jb ^ axr[i]) << 4));
#pragma unroll
            for (int g = 0; g < 4; g++)
                ldm4(bf[0][g], bB + boff[g] + (uint32_t)((jb ^ bxr[g]) << 4));
        }
#pragma unroll
        for (int s = 0; s < 4; s++) {
            const int cur = s & 1, nxt = cur ^ 1;
            if (s < 3) {
                const int jb = 2 * (s + 1) + h;
#pragma unroll
                for (int i = 0; i < 4; i++)
                    ldm4(af[nxt][i], aB + aoff[i] + (uint32_t)((jb ^ axr[i]) << 4));
#pragma unroll
                for (int g = 0; g < 4; g++)
                    ldm4(bf[nxt][g], bB + boff[g] + (uint32_t)((jb ^ bxr[g]) << 4));
            }
#pragma unroll
            for (int mi = 0; mi < 4; mi++)
#pragma unroll
                for (int g = 0; g < 4; g++) {
                    mma_op<DT>(acc[mi][2 * g],     af[cur][mi], bf[cur][g][0], bf[cur][g][2]);
                    mma_op<DT>(acc[mi][2 * g + 1], af[cur][mi], bf[cur][g][1], bf[cur][g][3]);
                }
        }
    }

    // epilogue
    const long long rowBase = (long long)blockIdx.z * cBatchRows + cRowOff + bm0 + wm * 64;
    const int colW = (int)bn0 + wn * 64;
#pragma unroll
    for (int mi = 0; mi < 4; mi++) {
        const long long r0 = rowBase + mi * 16 + (lid >> 2);
        const long long r1 = r0 + 8;
#pragma unroll
        for (int nj = 0; nj < 8; nj++) {
            const int col = colW + nj * 8 + (lid & 3) * 2;
            float b0 = 0.f, b1 = 0.f;
            if (bias) { b0 = bias[col]; b1 = bias[col + 1]; }
            const float v00 = acc[mi][nj][0] + b0, v01 = acc[mi][nj][1] + b1;
            const float v10 = acc[mi][nj][2] + b0, v11 = acc[mi][nj][3] + b1;
            if (C) {
                *(float2*)&C[r0 * N + col] = make_float2(v00, v01);
                *(float2*)&C[r1 * N + col] = make_float2(v10, v11);
            }
            if (sA3) {
                unsigned short h0 = bf16bits(v00), h1 = bf16bits(v01);
                ushort2 H = { h0, h1 };
                ushort2 L = { bf16bits(v00 - bf16val(h0)), bf16bits(v01 - bf16val(h1)) };
                unsigned short* sr = (unsigned short*)(sA3 + r0 * (3LL * N));
                *(ushort2*)(sr + col) = H;
                *(ushort2*)(sr + N + col) = H;
                *(ushort2*)(sr + 2LL * N + col) = L;
                h0 = bf16bits(v10); h1 = bf16bits(v11);
                H = { h0, h1 };
                L = { bf16bits(v10 - bf16val(h0)), bf16bits(v11 - bf16val(h1)) };
                sr = (unsigned short*)(sA3 + r1 * (3LL * N));
                *(ushort2*)(sr + col) = H;
                *(ushort2*)(sr + N + col) = H;
                *(ushort2*)(sr + 2LL * N + col) = L;
            }
            if (sH) {
                *(__half2*)&sH[r0 * N + col] = __floats2half2_rn(v00, v01);
                *(__half2*)&sH[r1 * N + col] = __floats2half2_rn(v10, v11);
            }
        }
    }
}

// ======================= split / convert / transpose kernels =================
// Fused: x -> xs (hi,hi,lo 3-seg bf16) AND xh (fp16), single read of x.
__global__ void split_cvt_x(const float* __restrict__ in, __nv_bfloat16* __restrict__ out3,
                            __half* __restrict__ outh, long long R, int K)
{
    const long long total = R * (long long)(K >> 2);
    const int K4 = K >> 2;
    for (long long i = (long long)blockIdx.x * blockDim.x + threadIdx.x;
         i < total; i += (long long)gridDim.x * blockDim.x) {
        const long long r = i / K4;
        const int k = (int)(i - r * K4) << 2;
        const float4 v = ((const float4*)in)[i];
        ushort4 H, L;
        H.x = bf16bits(v.x); L.x = bf16bits(v.x - bf16val(H.x));
        H.y = bf16bits(v.y); L.y = bf16bits(v.y - bf16val(H.y));
        H.z = bf16bits(v.z); L.z = bf16bits(v.z - bf16val(H.z));
        H.w = bf16bits(v.w); L.w = bf16bits(v.w - bf16val(H.w));
        unsigned short* row = (unsigned short*)(out3 + r * (3LL * K));
        *(ushort4*)(row + k) = H;
        *(ushort4*)(row + K + k) = H;
        *(ushort4*)(row + 2 * K + k) = L;
        __half2* ho = (__half2*)(outh + r * (long long)K + k);
        ho[0] = __floats2half2_rn(v.x, v.y);
        ho[1] = __floats2half2_rn(v.z, v.w);
    }
}

// B-operand split (hi,lo,hi)
__global__ void split_rows_b(const float* __restrict__ in, __nv_bfloat16* __restrict__ out,
                             long long R, int K)
{
    const long long total = R * (long long)(K >> 2);
    const int K4 = K >> 2;
    for (long long i = (long long)blockIdx.x * blockDim.x + threadIdx.x;
         i < total; i += (long long)gridDim.x * blockDim.x) {
        const long long r = i / K4;
        const int k = (int)(i - r * K4) << 2;
        const float4 v = ((const float4*)in)[i];
        ushort4 H, L;
        H.x = bf16bits(v.x); L.x = bf16bits(v.x - bf16val(H.x));
        H.y = bf16bits(v.y); L.y = bf16bits(v.y - bf16val(H.y));
        H.z = bf16bits(v.z); L.z = bf16bits(v.z - bf16val(H.z));
        H.w = bf16bits(v.w); L.w = bf16bits(v.w - bf16val(H.w));
        unsigned short* row = (unsigned short*)(out + r * (3LL * K));
        *(ushort4*)(row + k) = H;
        *(ushort4*)(row + K + k) = L;
        *(ushort4*)(row + 2 * K + k) = H;
    }
}

// fp32 [Kd, Nd] -> bf16 [Nd, 3*Kd] segments (hi,lo,hi). 64x64 tiles.
__global__ void transpose_split(const float* __restrict__ in, __nv_bfloat16* __restrict__ out,
                                int Kd, int Nd)
{
    __shared__ float s[64][65];
    const int k0 = blockIdx.y * 64, n0 = blockIdx.x * 64;
    const int tx = threadIdx.x & 63, ty = threadIdx.x >> 6;   // 256 threads
    for (int i = ty; i < 64; i += 4)
        s[i][tx] = in[(long long)(k0 + i) * Nd + n0 + tx];
    __syncthreads();
    for (int i = ty; i < 64; i += 4) {
        const int n = n0 + i, k = k0 + tx;
        const float v = s[tx][i];
        const unsigned short hb = bf16bits(v);
        const unsigned short lb = bf16bits(v - bf16val(hb));
        unsigned short* row = (unsigned short*)(out + (long long)n * (3LL * Kd));
        row[k] = hb; row[Kd + k] = lb; row[2 * Kd + k] = hb;
    }
}

// fp32 [Kd, Nd] -> fp16 [Nd, Kd]. 64x64 tiles.
__global__ void transpose_h(const float* __restrict__ in, __half* __restrict__ out,
                            int Kd, int Nd, long long inBatch, long long outBatch)
{
    __shared__ float s[64][65];
    in  += (long long)blockIdx.z * inBatch;
    out += (long long)blockIdx.z * outBatch;
    const int k0 = blockIdx.y * 64, n0 = blockIdx.x * 64;
    const int tx = threadIdx.x & 63, ty = threadIdx.x >> 6;
    for (int i = ty; i < 64; i += 4)
        s[i][tx] = in[(long long)(k0 + i) * Nd + n0 + tx];
    __syncthreads();
    for (int i = ty; i < 64; i += 4)
        out[(long long)(n0 + i) * Kd + k0 + tx] = __float2half_rn(s[tx][i]);
}

// ======================= softmax over QUERY axis -> fp16 =====================
// 2.5 passes: max; exp->fp16 store + sum; scale in place.
__global__ void softmax_h(const float* __restrict__ s, __half* __restrict__ attnh)
{
    const int col = blockIdx.x * blockDim.x + threadIdx.x;
    const int b = blockIdx.y;
    const float* base = s + (long long)b * SQ * KVLEN + col;
    float mx = -1e30f;
    for (int r = 0; r < SQ; r++) mx = fmaxf(mx, base[(long long)r * KVLEN]);
    __half* a = attnh + (long long)b * SQ * KVLEN + col;
    float sum = 0.f;
    for (int r = 0; r < SQ; r++) {
        const float e = __expf(base[(long long)r * KVLEN] - mx);
        a[(long long)r * KVLEN] = __float2half_rn(e);
        sum += e;
    }
    const float inv = 1.f / sum;
    for (int r = 0; r < SQ; r++) {
        const long long idx = (long long)r * KVLEN;
        a[idx] = __float2half_rn(__half2float(a[idx]) * inv);
    }
}

// ======================= KV cache copy =======================================
__global__ void cache_copy(const float* __restrict__ kc, const float* __restrict__ vc,
                           float* __restrict__ kout, float* __restrict__ vout)
{
    const long long per = (long long)PAST * DH / 4;
    const long long tot = per * NB;
    for (long long i = (long long)blockIdx.x * blockDim.x + threadIdx.x;
         i < tot; i += (long long)gridDim.x * blockDim.x) {
        const int b = (int)(i / per);
        const long long o = i - (long long)b * per;
        const long long dst = (long long)b * ((long long)KVLEN * DH / 4) + o;
        ((float4*)kout)[dst] = ((const float4*)kc)[i];
        ((float4*)vout)[dst] = ((const float4*)vc)[i];
    }
}

// =============================================================================
extern "C" void kernel_launch(void* const* d_in, const int* in_sizes, int n_in,
                              void* d_out, int out_size)
{
    const float* x    = (const float*)d_in[0];
    const float* kc   = (const float*)d_in[1];
    const float* vc   = (const float*)d_in[2];
    const float* Wq   = (const float*)d_in[3];
    const float* bq   = (const float*)d_in[4];
    const float* Wk   = (const float*)d_in[5];
    const float* bk   = (const float*)d_in[6];
    const float* Wv   = (const float*)d_in[7];
    const float* bv   = (const float*)d_in[8];
    const float* Wff  = (const float*)d_in[9];
    const float* bff  = (const float*)d_in[10];
    const float* Wout = (const float*)d_in[11];
    const float* bout = (const float*)d_in[12];

    float* out  = (float*)d_out;
    float* kout = out  + (long long)NB * SQ * DH;
    float* vout = kout + (long long)NB * KVLEN * DH;

    void* p;
    cudaGetSymbolAddress(&p, g_scores); float* scores = (float*)p;
    cudaGetSymbolAddress(&p, g_xs);    __nv_bfloat16* xs  = (__nv_bfloat16*)p;
    cudaGetSymbolAddress(&p, g_qs);    __nv_bfloat16* qs  = (__nv_bfloat16*)p;
    cudaGetSymbolAddress(&p, g_ks);    __nv_bfloat16* ks  = (__nv_bfloat16*)p;
    cudaGetSymbolAddress(&p, g_wqs);   __nv_bfloat16* wqs = (__nv_bfloat16*)p;
    cudaGetSymbolAddress(&p, g_wks);   __nv_bfloat16* wks = (__nv_bfloat16*)p;
    cudaGetSymbolAddress(&p, g_xh);    __half* xh    = (__half*)p;
    cudaGetSymbolAddress(&p, g_wvh);   __half* wvh   = (__half*)p;
    cudaGetSymbolAddress(&p, g_wffh);  __half* wffh  = (__half*)p;
    cudaGetSymbolAddress(&p, g_wouth); __half* wouth = (__half*)p;
    cudaGetSymbolAddress(&p, g_vth);   __half* vth   = (__half*)p;
    cudaGetSymbolAddress(&p, g_attnh); __half* attnh = (__half*)p;
    cudaGetSymbolAddress(&p, g_ctxh);  __half* ctxh  = (__half*)p;
    cudaGetSymbolAddress(&p, g_ffh);   __half* ffh   = (__half*)p;

    cudaFuncSetAttribute(gemm_tc<0>, cudaFuncAttributeMaxDynamicSharedMemorySize, SMEM_GEMM);
    cudaFuncSetAttribute(gemm_tc<1>, cudaFuncAttributeMaxDynamicSharedMemorySize, SMEM_GEMM);

    const int M = NB * SQ;  // 8192

    // 0) operand prep
    split_cvt_x<<<2048, 256>>>(x, xs, xh, (long long)M, DIN);
    transpose_split<<<dim3(DH / 64, DIN / 64, 1), 256>>>(Wq, wqs, DIN, DH);
    transpose_split<<<dim3(DH / 64, DIN / 64, 1), 256>>>(Wk, wks, DIN, DH);
    transpose_h<<<dim3(DH / 64, DIN / 64, 1), 256>>>(Wv, wvh, DIN, DH, 0, 0);
    transpose_h<<<dim3(DFF / 64, DH / 64, 1), 256>>>(Wff, wffh, DH, DFF, 0, 0);
    transpose_h<<<dim3(DH / 64, DFF / 64, 1), 256>>>(Wout, wouth, DFF, DH, 0, 0);
    cache_copy<<<2048, 256>>>(kc, vc, kout, vout);

    // 1) projections: q,k bf16x3 (K'=6144); v plain fp16 (K=2048)
    gemm_tc<0><<<dim3(DH / 128, M / 128, 1), 128, SMEM_GEMM>>>(
        (const uint16_t*)xs, (const uint16_t*)wqs, bq, nullptr, qs, nullptr,
        DH, 3 * DIN, 0, 0, M, 0);
    gemm_tc<0><<<dim3(DH / 128, SQ / 128, NB), 128, SMEM_GEMM>>>(
        (const uint16_t*)xs, (const uint16_t*)wks, bk, kout, nullptr, nullptr,
        DH, 3 * DIN, (long long)SQ * 3 * DIN, 0, KVLEN, PAST);
    gemm_tc<1><<<dim3(DH / 128, SQ / 128, NB), 128, SMEM_GEMM>>>(
        (const uint16_t*)xh, (const uint16_t*)wvh, bv, vout, nullptr, nullptr,
        DH, DIN, (long long)SQ * DIN, 0, KVLEN, PAST);

    // 2) K cache -> bf16 B-split; V cache -> fp16 transpose
    split_rows_b<<<2048, 256>>>(kout, ks, (long long)NB * KVLEN, DH);
    transpose_h<<<dim3(DH / 64, KVLEN / 64, NB), 256>>>(
        vout, vth, KVLEN, DH, (long long)KVLEN * DH, (long long)DH * KVLEN);

    // 3) scores = q' @ k'^T  (bf16x3, K'=6144)
    gemm_tc<0><<<dim3(KVLEN / 128, SQ / 128, NB), 128, SMEM_GEMM>>>(
        (const uint16_t*)qs, (const uint16_t*)ks, nullptr, scores, nullptr, nullptr,
        KVLEN, 3 * DH, (long long)SQ * 3 * DH, (long long)KVLEN * 3 * DH, SQ, 0);

    // 4) softmax over query axis -> fp16 attn
    softmax_h<<<dim3(KVLEN / 256, NB), 256>>>(scores, attnh);

    // 5) ctx = attn @ v  (fp16, K=4096) -> fp16 ctx
    gemm_tc<1><<<dim3(DH / 128, SQ / 128, NB), 128, SMEM_GEMM>>>(
        (const uint16_t*)attnh, (const uint16_t*)vth, nullptr, nullptr, nullptr, ctxh,
        DH, KVLEN, (long long)SQ * KVLEN, (long long)DH * KVLEN, SQ, 0);

    // 6) FFN (fp16): ff = ctx @ Wff^T + bff ; out = ff @ Wout^T + bout
    gemm_tc<1><<<dim3(DFF / 128, M / 128, 1), 128, SMEM_GEMM>>>(
        (const uint16_t*)ctxh, (const uint16_t*)wffh, bff, nullptr, nullptr, ffh,
        DFF, DH, 0, 0, M, 0);
    gemm_tc<1><<<dim3(DH / 128, M / 128, 1), 128, SMEM_GEMM>>>(
        (const uint16_t*)ffh, (const uint16_t*)wouth, bout, out, nullptr, nullptr,
        DH, DFF, 0, 0, M, 0);
}

// round 10
// speedup vs baseline: 1.4046x; 1.4046x over previous
#include <cuda_runtime.h>
#include <cuda_bf16.h>
#include <cuda_fp16.h>
#include <cstdint>

#define NB    4
#define SQ    2048
#define PAST  2048
#define DIN   2048
#define DH    2048
#define DFF   8192
#define KVLEN (PAST + SQ)   // 4096

// ======================= device scratch (no allocation) ======================
__device__ float g_scores[(long long)NB * SQ * KVLEN];
__device__ __nv_bfloat16 g_xs [(long long)NB*SQ * 3*DIN];
__device__ __nv_bfloat16 g_qs [(long long)NB*SQ * 3*DH];
__device__ __nv_bfloat16 g_ks [(long long)NB*KVLEN * 3*DH];
__device__ __nv_bfloat16 g_wqs[(long long)DH * 3*DIN];
__device__ __nv_bfloat16 g_wks[(long long)DH * 3*DIN];
__device__ __half g_xh   [(long long)NB*SQ * DIN];
__device__ __half g_wvh  [(long long)DH * DIN];
__device__ __half g_wffh [(long long)DFF * DH];
__device__ __half g_wouth[(long long)DH * DFF];
__device__ __half g_vth  [(long long)NB * DH * KVLEN];
__device__ __half g_attnh[(long long)NB * SQ * KVLEN];
__device__ __half g_ctxh [(long long)NB * SQ * DH];
__device__ __half g_ffh  [(long long)NB * SQ * DFF];

// ======================= helpers =============================================
__device__ __forceinline__ uint32_t smem_u32(const void* p) {
    uint32_t a;
    asm("{ .reg .u64 t; cvta.to.shared.u64 t, %1; cvt.u32.u64 %0, t; }" : "=r"(a) : "l"(p));
    return a;
}
__device__ __forceinline__ void ldm4(uint32_t* f, uint32_t a) {
    asm volatile("ldmatrix.sync.aligned.m8n8.x4.shared.b16 {%0,%1,%2,%3}, [%4];"
                 : "=r"(f[0]), "=r"(f[1]), "=r"(f[2]), "=r"(f[3]) : "r"(a));
}
template<int DT>   // 0 = bf16, 1 = f16
__device__ __forceinline__ void mma_op(float* c, const uint32_t* a, uint32_t b0, uint32_t b1) {
    if (DT == 0)
        asm volatile("mma.sync.aligned.m16n8k16.row.col.f32.bf16.bf16.f32 "
                     "{%0,%1,%2,%3}, {%4,%5,%6,%7}, {%8,%9}, {%0,%1,%2,%3};"
                     : "+f"(c[0]), "+f"(c[1]), "+f"(c[2]), "+f"(c[3])
                     : "r"(a[0]), "r"(a[1]), "r"(a[2]), "r"(a[3]), "r"(b0), "r"(b1));
    else
        asm volatile("mma.sync.aligned.m16n8k16.row.col.f32.f16.f16.f32 "
                     "{%0,%1,%2,%3}, {%4,%5,%6,%7}, {%8,%9}, {%0,%1,%2,%3};"
                     : "+f"(c[0]), "+f"(c[1]), "+f"(c[2]), "+f"(c[3])
                     : "r"(a[0]), "r"(a[1]), "r"(a[2]), "r"(a[3]), "r"(b0), "r"(b1));
}
__device__ __forceinline__ unsigned short bf16bits(float f) {
    __nv_bfloat16 h = __float2bfloat16(f);
    return *reinterpret_cast<unsigned short*>(&h);
}
__device__ __forceinline__ float bf16val(unsigned short u) {
    __nv_bfloat16 h = *reinterpret_cast<__nv_bfloat16*>(&u);
    return __bfloat162float(h);
}
__device__ __forceinline__ uint32_t swz(int r, int j) {   // 16B seg j in 64B row r
    return (uint32_t)(r * 64 + ((j ^ ((r >> 1) & 3)) << 4));
}
#define CP16(dst, src) asm volatile("cp.async.ca.shared.global [%0], [%1], 16;" :: "r"(dst), "l"(src) : "memory")
#define CP_COMMIT()    asm volatile("cp.async.commit_group;" ::: "memory")

// ======================= GEMM: C[M,N] = A[M,K]·B[N,K]^T =====================
// CTA 128x128. 128 threads = 4 warps (2M x 2N), warp tile 64x64.
// k-chunk 64 = two R8-layout k32 halves per stage. Stage 32KB:
//   [A half0 8KB][A half1 8KB][B half0 8KB][B half1 8KB]
// 3-stage cp.async (96KB dynamic) -> 2 CTAs/SM. R8 fragment math unchanged.
#define STG   32768
#define SMEM_GEMM (3 * STG)   // 98304

template<int DT>
__global__ void __launch_bounds__(128, 2)
gemm_tc(const uint16_t* __restrict__ A, const uint16_t* __restrict__ B,
        const float* __restrict__ bias, float* __restrict__ C,
        __nv_bfloat16* __restrict__ sA3, __half* __restrict__ sH,
        int N, long long Kp,
        long long aBatch, long long bBatch,
        int cBatchRows, int cRowOff)
{
    extern __shared__ __align__(16) uint8_t smem[];
    const uint32_t sb = smem_u32(smem);

    const int tid = threadIdx.x;
    const int wid = tid >> 5;
    const int lid = tid & 31;
    const long long bn0 = (long long)blockIdx.x * 128;
    const long long bm0 = (long long)blockIdx.y * 128;

    A += (long long)blockIdx.z * aBatch + bm0 * Kp;
    B += (long long)blockIdx.z * bBatch + bn0 * Kp;

    // loaders: per k32 half, 512 segs per operand, 4 per thread (128 threads)
    const uint16_t* aG[4];
    const uint16_t* bG[4];
    uint32_t sa[4];
#pragma unroll
    for (int i = 0; i < 4; i++) {
        const int u = tid + i * 128;
        const int r = u >> 2, j = u & 3;
        aG[i] = A + (long long)r * Kp + j * 8;
        bG[i] = B + (long long)r * Kp + j * 8;
        sa[i] = swz(r, j);
    }

    const int nT = (int)(Kp >> 6);   // k64 chunks

    auto ldStage = [&](int slot, int chunk) {
        const uint32_t st = sb + slot * STG;
#pragma unroll
        for (int h = 0; h < 2; h++) {
            const long long o = (long long)chunk * 64 + h * 32;
            const uint32_t ab = st + h * 8192;
            const uint32_t bb = st + 16384 + h * 8192;
#pragma unroll
            for (int i = 0; i < 4; i++) CP16(ab + sa[i], aG[i] + o);
#pragma unroll
            for (int i = 0; i < 4; i++) CP16(bb + sa[i], bG[i] + o);
        }
        CP_COMMIT();
    };
    ldStage(0, 0);
    ldStage(1, 1);

    // fragment addressing: warp (wm, wn), tile 64x64 (identical to R8)
    const int wm = wid & 1, wn = wid >> 1;
    const int l15 = lid & 15, h = lid >> 4;
    uint32_t aoff[4]; int ax[4];
#pragma unroll
    for (int i = 0; i < 4; i++) {
        const int r = wm * 64 + i * 16 + l15;
        aoff[i] = r * 64; ax[i] = (r >> 1) & 3;
    }
    uint32_t boff[4]; int bx[4];
#pragma unroll
    for (int g = 0; g < 4; g++) {
        const int r = wn * 64 + g * 16 + l15;
        boff[g] = r * 64; bx[g] = (r >> 1) & 3;
    }

    float acc[4][8][4];
#pragma unroll
    for (int i = 0; i < 4; i++)
#pragma unroll
        for (int j = 0; j < 8; j++)
#pragma unroll
            for (int k = 0; k < 4; k++) acc[i][j][k] = 0.f;

    for (int t = 0; t < nT; t++) {
        if (t + 1 < nT) asm volatile("cp.async.wait_group 1;" ::: "memory");
        else            asm volatile("cp.async.wait_group 0;" ::: "memory");
        __syncthreads();
        if (t + 2 < nT) ldStage((t + 2) % 3, t + 2);

        const uint32_t st = sb + (t % 3) * STG;
#pragma unroll
        for (int hh = 0; hh < 2; hh++) {
            const uint32_t aB = st + hh * 8192;
            const uint32_t bB = st + 16384 + hh * 8192;
#pragma unroll
            for (int s = 0; s < 2; s++) {
                uint32_t af[4][4], bfr[4][4];
                const int jb = 2 * s + h;
#pragma unroll
                for (int i = 0; i < 4; i++)
                    ldm4(af[i], aB + aoff[i] + (uint32_t)((jb ^ ax[i]) << 4));
#pragma unroll
                for (int g = 0; g < 4; g++)
                    ldm4(bfr[g], bB + boff[g] + (uint32_t)((jb ^ bx[g]) << 4));
#pragma unroll
                for (int mi = 0; mi < 4; mi++)
#pragma unroll
                    for (int g = 0; g < 4; g++) {
                        mma_op<DT>(acc[mi][2 * g],     af[mi], bfr[g][0], bfr[g][2]);
                        mma_op<DT>(acc[mi][2 * g + 1], af[mi], bfr[g][1], bfr[g][3]);
                    }
            }
        }
    }

    // epilogue (identical to R8)
    const long long rowBase = (long long)blockIdx.z * cBatchRows + cRowOff + bm0 + wm * 64;
    const int colW = (int)bn0 + wn * 64;
#pragma unroll
    for (int mi = 0; mi < 4; mi++) {
        const long long r0 = rowBase + mi * 16 + (lid >> 2);
        const long long r1 = r0 + 8;
#pragma unroll
        for (int nj = 0; nj < 8; nj++) {
            const int col = colW + nj * 8 + (lid & 3) * 2;
            float b0 = 0.f, b1 = 0.f;
            if (bias) { b0 = bias[col]; b1 = bias[col + 1]; }
            const float v00 = acc[mi][nj][0] + b0, v01 = acc[mi][nj][1] + b1;
            const float v10 = acc[mi][nj][2] + b0, v11 = acc[mi][nj][3] + b1;
            if (C) {
                *(float2*)&C[r0 * N + col] = make_float2(v00, v01);
                *(float2*)&C[r1 * N + col] = make_float2(v10, v11);
            }
            if (sA3) {
                unsigned short h0 = bf16bits(v00), h1 = bf16bits(v01);
                ushort2 H = { h0, h1 };
                ushort2 L = { bf16bits(v00 - bf16val(h0)), bf16bits(v01 - bf16val(h1)) };
                unsigned short* sr = (unsigned short*)(sA3 + r0 * (3LL * N));
                *(ushort2*)(sr + col) = H;
                *(ushort2*)(sr + N + col) = H;
                *(ushort2*)(sr + 2LL * N + col) = L;
                h0 = bf16bits(v10); h1 = bf16bits(v11);
                H = { h0, h1 };
                L = { bf16bits(v10 - bf16val(h0)), bf16bits(v11 - bf16val(h1)) };
                sr = (unsigned short*)(sA3 + r1 * (3LL * N));
                *(ushort2*)(sr + col) = H;
                *(ushort2*)(sr + N + col) = H;
                *(ushort2*)(sr + 2LL * N + col) = L;
            }
            if (sH) {
                *(__half2*)&sH[r0 * N + col] = __floats2half2_rn(v00, v01);
                *(__half2*)&sH[r1 * N + col] = __floats2half2_rn(v10, v11);
            }
        }
    }
}

// ======================= split / convert / transpose kernels =================
// Fused: x -> xs (hi,hi,lo 3-seg bf16) AND xh (fp16), single read of x.
__global__ void split_cvt_x(const float* __restrict__ in, __nv_bfloat16* __restrict__ out3,
                            __half* __restrict__ outh, long long R, int K)
{
    const long long total = R * (long long)(K >> 2);
    const int K4 = K >> 2;
    for (long long i = (long long)blockIdx.x * blockDim.x + threadIdx.x;
         i < total; i += (long long)gridDim.x * blockDim.x) {
        const long long r = i / K4;
        const int k = (int)(i - r * K4) << 2;
        const float4 v = ((const float4*)in)[i];
        ushort4 H, L;
        H.x = bf16bits(v.x); L.x = bf16bits(v.x - bf16val(H.x));
        H.y = bf16bits(v.y); L.y = bf16bits(v.y - bf16val(H.y));
        H.z = bf16bits(v.z); L.z = bf16bits(v.z - bf16val(H.z));
        H.w = bf16bits(v.w); L.w = bf16bits(v.w - bf16val(H.w));
        unsigned short* row = (unsigned short*)(out3 + r * (3LL * K));
        *(ushort4*)(row + k) = H;
        *(ushort4*)(row + K + k) = H;
        *(ushort4*)(row + 2 * K + k) = L;
        __half2* ho = (__half2*)(outh + r * (long long)K + k);
        ho[0] = __floats2half2_rn(v.x, v.y);
        ho[1] = __floats2half2_rn(v.z, v.w);
    }
}

// B-operand split (hi,lo,hi)
__global__ void split_rows_b(const float* __restrict__ in, __nv_bfloat16* __restrict__ out,
                             long long R, int K)
{
    const long long total = R * (long long)(K >> 2);
    const int K4 = K >> 2;
    for (long long i = (long long)blockIdx.x * blockDim.x + threadIdx.x;
         i < total; i += (long long)gridDim.x * blockDim.x) {
        const long long r = i / K4;
        const int k = (int)(i - r * K4) << 2;
        const float4 v = ((const float4*)in)[i];
        ushort4 H, L;
        H.x = bf16bits(v.x); L.x = bf16bits(v.x - bf16val(H.x));
        H.y = bf16bits(v.y); L.y = bf16bits(v.y - bf16val(H.y));
        H.z = bf16bits(v.z); L.z = bf16bits(v.z - bf16val(H.z));
        H.w = bf16bits(v.w); L.w = bf16bits(v.w - bf16val(H.w));
        unsigned short* row = (unsigned short*)(out + r * (3LL * K));
        *(ushort4*)(row + k) = H;
        *(ushort4*)(row + K + k) = L;
        *(ushort4*)(row + 2 * K + k) = H;
    }
}

// fp32 [Kd, Nd] -> bf16 [Nd, 3*Kd] segments (hi,lo,hi). 64x64 tiles.
__global__ void transpose_split(const float* __restrict__ in, __nv_bfloat16* __restrict__ out,
                                int Kd, int Nd)
{
    __shared__ float s[64][65];
    const int k0 = blockIdx.y * 64, n0 = blockIdx.x * 64;
    const int tx = threadIdx.x & 63, ty = threadIdx.x >> 6;   // 256 threads
    for (int i = ty; i < 64; i += 4)
        s[i][tx] = in[(long long)(k0 + i) * Nd + n0 + tx];
    __syncthreads();
    for (int i = ty; i < 64; i += 4) {
        const int n = n0 + i, k = k0 + tx;
        const float v = s[tx][i];
        const unsigned short hb = bf16bits(v);
        const unsigned short lb = bf16bits(v - bf16val(hb));
        unsigned short* row = (unsigned short*)(out + (long long)n * (3LL * Kd));
        row[k] = hb; row[Kd + k] = lb; row[2 * Kd + k] = hb;
    }
}

// fp32 [Kd, Nd] -> fp16 [Nd, Kd]. 64x64 tiles.
__global__ void transpose_h(const float* __restrict__ in, __half* __restrict__ out,
                            int Kd, int Nd, long long inBatch, long long outBatch)
{
    __shared__ float s[64][65];
    in  += (long long)blockIdx.z * inBatch;
    out += (long long)blockIdx.z * outBatch;
    const int k0 = blockIdx.y * 64, n0 = blockIdx.x * 64;
    const int tx = threadIdx.x & 63, ty = threadIdx.x >> 6;
    for (int i = ty; i < 64; i += 4)
        s[i][tx] = in[(long long)(k0 + i) * Nd + n0 + tx];
    __syncthreads();
    for (int i = ty; i < 64; i += 4)
        out[(long long)(n0 + i) * Kd + k0 + tx] = __float2half_rn(s[tx][i]);
}

// ======================= softmax over QUERY axis -> fp16 =====================
__global__ void softmax_h(const float* __restrict__ s, __half* __restrict__ attnh)
{
    const int col = blockIdx.x * blockDim.x + threadIdx.x;
    const int b = blockIdx.y;
    const float* base = s + (long long)b * SQ * KVLEN + col;
    float mx = -1e30f;
    for (int r = 0; r < SQ; r++) mx = fmaxf(mx, base[(long long)r * KVLEN]);
    __half* a = attnh + (long long)b * SQ * KVLEN + col;
    float sum = 0.f;
    for (int r = 0; r < SQ; r++) {
        const float e = __expf(base[(long long)r * KVLEN] - mx);
        a[(long long)r * KVLEN] = __float2half_rn(e);
        sum += e;
    }
    const float inv = 1.f / sum;
    for (int r = 0; r < SQ; r++) {
        const long long idx = (long long)r * KVLEN;
        a[idx] = __float2half_rn(__half2float(a[idx]) * inv);
    }
}

// ======================= KV cache copy =======================================
__global__ void cache_copy(const float* __restrict__ kc, const float* __restrict__ vc,
                           float* __restrict__ kout, float* __restrict__ vout)
{
    const long long per = (long long)PAST * DH / 4;
    const long long tot = per * NB;
    for (long long i = (long long)blockIdx.x * blockDim.x + threadIdx.x;
         i < tot; i += (long long)gridDim.x * blockDim.x) {
        const int b = (int)(i / per);
        const long long o = i - (long long)b * per;
        const long long dst = (long long)b * ((long long)KVLEN * DH / 4) + o;
        ((float4*)kout)[dst] = ((const float4*)kc)[i];
        ((float4*)vout)[dst] = ((const float4*)vc)[i];
    }
}

// =============================================================================
extern "C" void kernel_launch(void* const* d_in, const int* in_sizes, int n_in,
                              void* d_out, int out_size)
{
    const float* x    = (const float*)d_in[0];
    const float* kc   = (const float*)d_in[1];
    const float* vc   = (const float*)d_in[2];
    const float* Wq   = (const float*)d_in[3];
    const float* bq   = (const float*)d_in[4];
    const float* Wk   = (const float*)d_in[5];
    const float* bk   = (const float*)d_in[6];
    const float* Wv   = (const float*)d_in[7];
    const float* bv   = (const float*)d_in[8];
    const float* Wff  = (const float*)d_in[9];
    const float* bff  = (const float*)d_in[10];
    const float* Wout = (const float*)d_in[11];
    const float* bout = (const float*)d_in[12];

    float* out  = (float*)d_out;
    float* kout = out  + (long long)NB * SQ * DH;
    float* vout = kout + (long long)NB * KVLEN * DH;

    void* p;
    cudaGetSymbolAddress(&p, g_scores); float* scores = (float*)p;
    cudaGetSymbolAddress(&p, g_xs);    __nv_bfloat16* xs  = (__nv_bfloat16*)p;
    cudaGetSymbolAddress(&p, g_qs);    __nv_bfloat16* qs  = (__nv_bfloat16*)p;
    cudaGetSymbolAddress(&p, g_ks);    __nv_bfloat16* ks  = (__nv_bfloat16*)p;
    cudaGetSymbolAddress(&p, g_wqs);   __nv_bfloat16* wqs = (__nv_bfloat16*)p;
    cudaGetSymbolAddress(&p, g_wks);   __nv_bfloat16* wks = (__nv_bfloat16*)p;
    cudaGetSymbolAddress(&p, g_xh);    __half* xh    = (__half*)p;
    cudaGetSymbolAddress(&p, g_wvh);   __half* wvh   = (__half*)p;
    cudaGetSymbolAddress(&p, g_wffh);  __half* wffh  = (__half*)p;
    cudaGetSymbolAddress(&p, g_wouth); __half* wouth = (__half*)p;
    cudaGetSymbolAddress(&p, g_vth);   __half* vth   = (__half*)p;
    cudaGetSymbolAddress(&p, g_attnh); __half* attnh = (__half*)p;
    cudaGetSymbolAddress(&p, g_ctxh);  __half* ctxh  = (__half*)p;
    cudaGetSymbolAddress(&p, g_ffh);   __half* ffh   = (__half*)p;

    cudaFuncSetAttribute(gemm_tc<0>, cudaFuncAttributeMaxDynamicSharedMemorySize, SMEM_GEMM);
    cudaFuncSetAttribute(gemm_tc<1>, cudaFuncAttributeMaxDynamicSharedMemorySize, SMEM_GEMM);

    const int M = NB * SQ;  // 8192

    // 0) operand prep
    split_cvt_x<<<2048, 256>>>(x, xs, xh, (long long)M, DIN);
    transpose_split<<<dim3(DH / 64, DIN / 64, 1), 256>>>(Wq, wqs, DIN, DH);
    transpose_split<<<dim3(DH / 64, DIN / 64, 1), 256>>>(Wk, wks, DIN, DH);
    transpose_h<<<dim3(DH / 64, DIN / 64, 1), 256>>>(Wv, wvh, DIN, DH, 0, 0);
    transpose_h<<<dim3(DFF / 64, DH / 64, 1), 256>>>(Wff, wffh, DH, DFF, 0, 0);
    transpose_h<<<dim3(DH / 64, DFF / 64, 1), 256>>>(Wout, wouth, DFF, DH, 0, 0);
    cache_copy<<<2048, 256>>>(kc, vc, kout, vout);

    // 1) projections: q,k bf16x3 (K'=6144); v plain fp16 (K=2048)
    gemm_tc<0><<<dim3(DH / 128, M / 128, 1), 128, SMEM_GEMM>>>(
        (const uint16_t*)xs, (const uint16_t*)wqs, bq, nullptr, qs, nullptr,
        DH, 3 * DIN, 0, 0, M, 0);
    gemm_tc<0><<<dim3(DH / 128, SQ / 128, NB), 128, SMEM_GEMM>>>(
        (const uint16_t*)xs, (const uint16_t*)wks, bk, kout, nullptr, nullptr,
        DH, 3 * DIN, (long long)SQ * 3 * DIN, 0, KVLEN, PAST);
    gemm_tc<1><<<dim3(DH / 128, SQ / 128, NB), 128, SMEM_GEMM>>>(
        (const uint16_t*)xh, (const uint16_t*)wvh, bv, vout, nullptr, nullptr,
        DH, DIN, (long long)SQ * DIN, 0, KVLEN, PAST);

    // 2) K cache -> bf16 B-split; V cache -> fp16 transpose
    split_rows_b<<<2048, 256>>>(kout, ks, (long long)NB * KVLEN, DH);
    transpose_h<<<dim3(DH / 64, KVLEN / 64, NB), 256>>>(
        vout, vth, KVLEN, DH, (long long)KVLEN * DH, (long long)DH * KVLEN);

    // 3) scores = q' @ k'^T  (bf16x3, K'=6144)
    gemm_tc<0><<<dim3(KVLEN / 128, SQ / 128, NB), 128, SMEM_GEMM>>>(
        (const uint16_t*)qs, (const uint16_t*)ks, nullptr, scores, nullptr, nullptr,
        KVLEN, 3 * DH, (long long)SQ * 3 * DH, (long long)KVLEN * 3 * DH, SQ, 0);

    // 4) softmax over query axis -> fp16 attn
    softmax_h<<<dim3(KVLEN / 256, NB), 256>>>(scores, attnh);

    // 5) ctx = attn @ v  (fp16, K=4096) -> fp16 ctx
    gemm_tc<1><<<dim3(DH / 128, SQ / 128, NB), 128, SMEM_GEMM>>>(
        (const uint16_t*)attnh, (const uint16_t*)vth, nullptr, nullptr, nullptr, ctxh,
        DH, KVLEN, (long long)SQ * KVLEN, (long long)DH * KVLEN, SQ, 0);

    // 6) FFN (fp16): ff = ctx @ Wff^T + bff ; out = ff @ Wout^T + bout
    gemm_tc<1><<<dim3(DFF / 128, M / 128, 1), 128, SMEM_GEMM>>>(
        (const uint16_t*)ctxh, (const uint16_t*)wffh, bff, nullptr, nullptr, ffh,
        DFF, DH, 0, 0, M, 0);
    gemm_tc<1><<<dim3(DH / 128, M / 128, 1), 128, SMEM_GEMM>>>(
        (const uint16_t*)ffh, (const uint16_t*)wouth, bout, out, nullptr, nullptr,
        DH, DFF, 0, 0, M, 0);
}

// round 11
// speedup vs baseline: 1.4326x; 1.0199x over previous
#include <cuda_runtime.h>
#include <cuda_bf16.h>
#include <cuda_fp16.h>
#include <cstdint>

#define NB    4
#define SQ    2048
#define PAST  2048
#define DIN   2048
#define DH    2048
#define DFF   8192
#define KVLEN (PAST + SQ)   // 4096

// ======================= device scratch (no allocation) ======================
__device__ float g_scores[(long long)NB * SQ * KVLEN];
__device__ __nv_bfloat16 g_xs [(long long)NB*SQ * 3*DIN];
__device__ __nv_bfloat16 g_qs [(long long)NB*SQ * 3*DH];
__device__ __nv_bfloat16 g_ks [(long long)NB*KVLEN * 3*DH];
__device__ __nv_bfloat16 g_wqs[(long long)DH * 3*DIN];
__device__ __nv_bfloat16 g_wks[(long long)DH * 3*DIN];
__device__ __half g_xh   [(long long)NB*SQ * DIN];
__device__ __half g_wvh  [(long long)DH * DIN];
__device__ __half g_wffh [(long long)DFF * DH];
__device__ __half g_wouth[(long long)DH * DFF];
__device__ __half g_vth  [(long long)NB * DH * KVLEN];
__device__ __half g_attnh[(long long)NB * SQ * KVLEN];
__device__ __half g_ctxh [(long long)NB * SQ * DH];
__device__ __half g_ffh  [(long long)NB * SQ * DFF];

// ======================= helpers =============================================
__device__ __forceinline__ uint32_t smem_u32(const void* p) {
    uint32_t a;
    asm("{ .reg .u64 t; cvta.to.shared.u64 t, %1; cvt.u32.u64 %0, t; }" : "=r"(a) : "l"(p));
    return a;
}
__device__ __forceinline__ void ldm4(uint32_t* f, uint32_t a) {
    asm volatile("ldmatrix.sync.aligned.m8n8.x4.shared.b16 {%0,%1,%2,%3}, [%4];"
                 : "=r"(f[0]), "=r"(f[1]), "=r"(f[2]), "=r"(f[3]) : "r"(a));
}
template<int DT>   // 0 = bf16, 1 = f16
__device__ __forceinline__ void mma_op(float* c, const uint32_t* a, uint32_t b0, uint32_t b1) {
    if (DT == 0)
        asm volatile("mma.sync.aligned.m16n8k16.row.col.f32.bf16.bf16.f32 "
                     "{%0,%1,%2,%3}, {%4,%5,%6,%7}, {%8,%9}, {%0,%1,%2,%3};"
                     : "+f"(c[0]), "+f"(c[1]), "+f"(c[2]), "+f"(c[3])
                     : "r"(a[0]), "r"(a[1]), "r"(a[2]), "r"(a[3]), "r"(b0), "r"(b1));
    else
        asm volatile("mma.sync.aligned.m16n8k16.row.col.f32.f16.f16.f32 "
                     "{%0,%1,%2,%3}, {%4,%5,%6,%7}, {%8,%9}, {%0,%1,%2,%3};"
                     : "+f"(c[0]), "+f"(c[1]), "+f"(c[2]), "+f"(c[3])
                     : "r"(a[0]), "r"(a[1]), "r"(a[2]), "r"(a[3]), "r"(b0), "r"(b1));
}
__device__ __forceinline__ unsigned short bf16bits(float f) {
    __nv_bfloat16 h = __float2bfloat16(f);
    return *reinterpret_cast<unsigned short*>(&h);
}
__device__ __forceinline__ float bf16val(unsigned short u) {
    __nv_bfloat16 h = *reinterpret_cast<__nv_bfloat16*>(&u);
    return __bfloat162float(h);
}
__device__ __forceinline__ uint32_t swz(int r, int j) {   // 16B seg j in 64B row r
    return (uint32_t)(r * 64 + ((j ^ ((r >> 1) & 3)) << 4));
}
#define CP16(dst, src) asm volatile("cp.async.ca.shared.global [%0], [%1], 16;" :: "r"(dst), "l"(src) : "memory")
#define CP_COMMIT()    asm volatile("cp.async.commit_group;" ::: "memory")

// ======================= GEMM (R10 winner, unchanged) ========================
// CTA 128x128, k-chunk 64 (two k32 halves per 32KB stage), 3 stages, 2 CTA/SM.
#define STG   32768
#define SMEM_GEMM (3 * STG)   // 98304

template<int DT>
__global__ void __launch_bounds__(128, 2)
gemm_tc(const uint16_t* __restrict__ A, const uint16_t* __restrict__ B,
        const float* __restrict__ bias, float* __restrict__ C,
        __nv_bfloat16* __restrict__ sA3, __half* __restrict__ sH,
        int N, long long Kp,
        long long aBatch, long long bBatch,
        int cBatchRows, int cRowOff)
{
    extern __shared__ __align__(16) uint8_t smem[];
    const uint32_t sb = smem_u32(smem);

    const int tid = threadIdx.x;
    const int wid = tid >> 5;
    const int lid = tid & 31;
    const long long bn0 = (long long)blockIdx.x * 128;
    const long long bm0 = (long long)blockIdx.y * 128;

    A += (long long)blockIdx.z * aBatch + bm0 * Kp;
    B += (long long)blockIdx.z * bBatch + bn0 * Kp;

    const uint16_t* aG[4];
    const uint16_t* bG[4];
    uint32_t sa[4];
#pragma unroll
    for (int i = 0; i < 4; i++) {
        const int u = tid + i * 128;
        const int r = u >> 2, j = u & 3;
        aG[i] = A + (long long)r * Kp + j * 8;
        bG[i] = B + (long long)r * Kp + j * 8;
        sa[i] = swz(r, j);
    }

    const int nT = (int)(Kp >> 6);

    auto ldStage = [&](int slot, int chunk) {
        const uint32_t st = sb + slot * STG;
#pragma unroll
        for (int h = 0; h < 2; h++) {
            const long long o = (long long)chunk * 64 + h * 32;
            const uint32_t ab = st + h * 8192;
            const uint32_t bb = st + 16384 + h * 8192;
#pragma unroll
            for (int i = 0; i < 4; i++) CP16(ab + sa[i], aG[i] + o);
#pragma unroll
            for (int i = 0; i < 4; i++) CP16(bb + sa[i], bG[i] + o);
        }
        CP_COMMIT();
    };
    ldStage(0, 0);
    ldStage(1, 1);

    const int wm = wid & 1, wn = wid >> 1;
    const int l15 = lid & 15, h = lid >> 4;
    uint32_t aoff[4]; int ax[4];
#pragma unroll
    for (int i = 0; i < 4; i++) {
        const int r = wm * 64 + i * 16 + l15;
        aoff[i] = r * 64; ax[i] = (r >> 1) & 3;
    }
    uint32_t boff[4]; int bx[4];
#pragma unroll
    for (int g = 0; g < 4; g++) {
        const int r = wn * 64 + g * 16 + l15;
        boff[g] = r * 64; bx[g] = (r >> 1) & 3;
    }

    float acc[4][8][4];
#pragma unroll
    for (int i = 0; i < 4; i++)
#pragma unroll
        for (int j = 0; j < 8; j++)
#pragma unroll
            for (int k = 0; k < 4; k++) acc[i][j][k] = 0.f;

    for (int t = 0; t < nT; t++) {
        if (t + 1 < nT) asm volatile("cp.async.wait_group 1;" ::: "memory");
        else            asm volatile("cp.async.wait_group 0;" ::: "memory");
        __syncthreads();
        if (t + 2 < nT) ldStage((t + 2) % 3, t + 2);

        const uint32_t st = sb + (t % 3) * STG;
#pragma unroll
        for (int hh = 0; hh < 2; hh++) {
            const uint32_t aB = st + hh * 8192;
            const uint32_t bB = st + 16384 + hh * 8192;
#pragma unroll
            for (int s = 0; s < 2; s++) {
                uint32_t af[4][4], bfr[4][4];
                const int jb = 2 * s + h;
#pragma unroll
                for (int i = 0; i < 4; i++)
                    ldm4(af[i], aB + aoff[i] + (uint32_t)((jb ^ ax[i]) << 4));
#pragma unroll
                for (int g = 0; g < 4; g++)
                    ldm4(bfr[g], bB + boff[g] + (uint32_t)((jb ^ bx[g]) << 4));
#pragma unroll
                for (int mi = 0; mi < 4; mi++)
#pragma unroll
                    for (int g = 0; g < 4; g++) {
                        mma_op<DT>(acc[mi][2 * g],     af[mi], bfr[g][0], bfr[g][2]);
                        mma_op<DT>(acc[mi][2 * g + 1], af[mi], bfr[g][1], bfr[g][3]);
                    }
            }
        }
    }

    const long long rowBase = (long long)blockIdx.z * cBatchRows + cRowOff + bm0 + wm * 64;
    const int colW = (int)bn0 + wn * 64;
#pragma unroll
    for (int mi = 0; mi < 4; mi++) {
        const long long r0 = rowBase + mi * 16 + (lid >> 2);
        const long long r1 = r0 + 8;
#pragma unroll
        for (int nj = 0; nj < 8; nj++) {
            const int col = colW + nj * 8 + (lid & 3) * 2;
            float b0 = 0.f, b1 = 0.f;
            if (bias) { b0 = bias[col]; b1 = bias[col + 1]; }
            const float v00 = acc[mi][nj][0] + b0, v01 = acc[mi][nj][1] + b1;
            const float v10 = acc[mi][nj][2] + b0, v11 = acc[mi][nj][3] + b1;
            if (C) {
                *(float2*)&C[r0 * N + col] = make_float2(v00, v01);
                *(float2*)&C[r1 * N + col] = make_float2(v10, v11);
            }
            if (sA3) {
                unsigned short h0 = bf16bits(v00), h1 = bf16bits(v01);
                ushort2 H = { h0, h1 };
                ushort2 L = { bf16bits(v00 - bf16val(h0)), bf16bits(v01 - bf16val(h1)) };
                unsigned short* sr = (unsigned short*)(sA3 + r0 * (3LL * N));
                *(ushort2*)(sr + col) = H;
                *(ushort2*)(sr + N + col) = H;
                *(ushort2*)(sr + 2LL * N + col) = L;
                h0 = bf16bits(v10); h1 = bf16bits(v11);
                H = { h0, h1 };
                L = { bf16bits(v10 - bf16val(h0)), bf16bits(v11 - bf16val(h1)) };
                sr = (unsigned short*)(sA3 + r1 * (3LL * N));
                *(ushort2*)(sr + col) = H;
                *(ushort2*)(sr + N + col) = H;
                *(ushort2*)(sr + 2LL * N + col) = L;
            }
            if (sH) {
                *(__half2*)&sH[r0 * N + col] = __floats2half2_rn(v00, v01);
                *(__half2*)&sH[r1 * N + col] = __floats2half2_rn(v10, v11);
            }
        }
    }
}

// ======================= prep kernels (division-free, exact grids) ===========
// x -> xs (hi,hi,lo) + xh (fp16). grid: (K/4/256, R); one float4/thread.
__global__ void split_cvt_x(const float* __restrict__ in, __nv_bfloat16* __restrict__ out3,
                            __half* __restrict__ outh, int K)
{
    const int k4 = blockIdx.x * blockDim.x + threadIdx.x;   // float4 index in row
    const long long r = blockIdx.y;
    const int k = k4 << 2;
    const float4 v = ((const float4*)(in + r * (long long)K))[k4];
    ushort4 H, L;
    H.x = bf16bits(v.x); L.x = bf16bits(v.x - bf16val(H.x));
    H.y = bf16bits(v.y); L.y = bf16bits(v.y - bf16val(H.y));
    H.z = bf16bits(v.z); L.z = bf16bits(v.z - bf16val(H.z));
    H.w = bf16bits(v.w); L.w = bf16bits(v.w - bf16val(H.w));
    unsigned short* row = (unsigned short*)(out3 + r * (3LL * K));
    *(ushort4*)(row + k) = H;
    *(ushort4*)(row + K + k) = H;
    *(ushort4*)(row + 2 * K + k) = L;
    __half2* ho = (__half2*)(outh + r * (long long)K + k);
    ho[0] = __floats2half2_rn(v.x, v.y);
    ho[1] = __floats2half2_rn(v.z, v.w);
}

// B-operand split (hi,lo,hi). grid: (K/4/256, R).
__global__ void split_rows_b(const float* __restrict__ in, __nv_bfloat16* __restrict__ out,
                             int K)
{
    const int k4 = blockIdx.x * blockDim.x + threadIdx.x;
    const long long r = blockIdx.y;
    const int k = k4 << 2;
    const float4 v = ((const float4*)(in + r * (long long)K))[k4];
    ushort4 H, L;
    H.x = bf16bits(v.x); L.x = bf16bits(v.x - bf16val(H.x));
    H.y = bf16bits(v.y); L.y = bf16bits(v.y - bf16val(H.y));
    H.z = bf16bits(v.z); L.z = bf16bits(v.z - bf16val(H.z));
    H.w = bf16bits(v.w); L.w = bf16bits(v.w - bf16val(H.w));
    unsigned short* row = (unsigned short*)(out + r * (3LL * K));
    *(ushort4*)(row + k) = H;
    *(ushort4*)(row + K + k) = L;
    *(ushort4*)(row + 2 * K + k) = H;
}

// past-cache copy. grid: (per4/256, NB); one float4/thread, no division.
__global__ void cache_copy(const float* __restrict__ kc, const float* __restrict__ vc,
                           float* __restrict__ kout, float* __restrict__ vout)
{
    const long long per4 = (long long)PAST * DH / 4;
    const int b = blockIdx.y;
    const long long o = (long long)blockIdx.x * blockDim.x + threadIdx.x;
    const long long src = (long long)b * per4 + o;
    const long long dst = (long long)b * ((long long)KVLEN * DH / 4) + o;
    ((float4*)kout)[dst] = ((const float4*)kc)[src];
    ((float4*)vout)[dst] = ((const float4*)vc)[src];
}

// fp32 [Kd, Nd] -> bf16 [Nd, 3*Kd] segments (hi,lo,hi). 64x64 tiles.
__global__ void transpose_split(const float* __restrict__ in, __nv_bfloat16* __restrict__ out,
                                int Kd, int Nd)
{
    __shared__ float s[64][65];
    const int k0 = blockIdx.y * 64, n0 = blockIdx.x * 64;
    const int tx = threadIdx.x & 63, ty = threadIdx.x >> 6;
    for (int i = ty; i < 64; i += 4)
        s[i][tx] = in[(long long)(k0 + i) * Nd + n0 + tx];
    __syncthreads();
    for (int i = ty; i < 64; i += 4) {
        const int n = n0 + i, k = k0 + tx;
        const float v = s[tx][i];
        const unsigned short hb = bf16bits(v);
        const unsigned short lb = bf16bits(v - bf16val(hb));
        unsigned short* row = (unsigned short*)(out + (long long)n * (3LL * Kd));
        row[k] = hb; row[Kd + k] = lb; row[2 * Kd + k] = hb;
    }
}

// fp32 [Kd, Nd] -> fp16 [Nd, Kd]. 64x64 tiles.
__global__ void transpose_h(const float* __restrict__ in, __half* __restrict__ out,
                            int Kd, int Nd, long long inBatch, long long outBatch)
{
    __shared__ float s[64][65];
    in  += (long long)blockIdx.z * inBatch;
    out += (long long)blockIdx.z * outBatch;
    const int k0 = blockIdx.y * 64, n0 = blockIdx.x * 64;
    const int tx = threadIdx.x & 63, ty = threadIdx.x >> 6;
    for (int i = ty; i < 64; i += 4)
        s[i][tx] = in[(long long)(k0 + i) * Nd + n0 + tx];
    __syncthreads();
    for (int i = ty; i < 64; i += 4)
        out[(long long)(n0 + i) * Kd + k0 + tx] = __float2half_rn(s[tx][i]);
}

// ======================= softmax over QUERY axis -> fp16 =====================
// block = (64 cols x 4 row-threads); grid = (KVLEN/64, NB). Coalesced 256B rows.
__global__ void softmax_h(const float* __restrict__ s, __half* __restrict__ attnh)
{
    __shared__ float red[4][64];
    const int tx = threadIdx.x & 63;
    const int ty = threadIdx.x >> 6;
    const int col = blockIdx.x * 64 + tx;
    const int b = blockIdx.y;
    const float* base = s + (long long)b * SQ * KVLEN + col;

    float mx = -1e30f;
    for (int r = ty; r < SQ; r += 4) mx = fmaxf(mx, base[(long long)r * KVLEN]);
    red[ty][tx] = mx;
    __syncthreads();
    mx = fmaxf(fmaxf(red[0][tx], red[1][tx]), fmaxf(red[2][tx], red[3][tx]));
    __syncthreads();

    __half* a = attnh + (long long)b * SQ * KVLEN + col;
    float sum = 0.f;
    for (int r = ty; r < SQ; r += 4) {
        const float e = __expf(base[(long long)r * KVLEN] - mx);
        a[(long long)r * KVLEN] = __float2half_rn(e);
        sum += e;
    }
    red[ty][tx] = sum;
    __syncthreads();
    sum = (red[0][tx] + red[1][tx]) + (red[2][tx] + red[3][tx]);
    const float inv = 1.f / sum;
    for (int r = ty; r < SQ; r += 4) {
        const long long idx = (long long)r * KVLEN;
        a[idx] = __float2half_rn(__half2float(a[idx]) * inv);
    }
}

// =============================================================================
extern "C" void kernel_launch(void* const* d_in, const int* in_sizes, int n_in,
                              void* d_out, int out_size)
{
    const float* x    = (const float*)d_in[0];
    const float* kc   = (const float*)d_in[1];
    const float* vc   = (const float*)d_in[2];
    const float* Wq   = (const float*)d_in[3];
    const float* bq   = (const float*)d_in[4];
    const float* Wk   = (const float*)d_in[5];
    const float* bk   = (const float*)d_in[6];
    const float* Wv   = (const float*)d_in[7];
    const float* bv   = (const float*)d_in[8];
    const float* Wff  = (const float*)d_in[9];
    const float* bff  = (const float*)d_in[10];
    const float* Wout = (const float*)d_in[11];
    const float* bout = (const float*)d_in[12];

    float* out  = (float*)d_out;
    float* kout = out  + (long long)NB * SQ * DH;
    float* vout = kout + (long long)NB * KVLEN * DH;

    void* p;
    cudaGetSymbolAddress(&p, g_scores); float* scores = (float*)p;
    cudaGetSymbolAddress(&p, g_xs);    __nv_bfloat16* xs  = (__nv_bfloat16*)p;
    cudaGetSymbolAddress(&p, g_qs);    __nv_bfloat16* qs  = (__nv_bfloat16*)p;
    cudaGetSymbolAddress(&p, g_ks);    __nv_bfloat16* ks  = (__nv_bfloat16*)p;
    cudaGetSymbolAddress(&p, g_wqs);   __nv_bfloat16* wqs = (__nv_bfloat16*)p;
    cudaGetSymbolAddress(&p, g_wks);   __nv_bfloat16* wks = (__nv_bfloat16*)p;
    cudaGetSymbolAddress(&p, g_xh);    __half* xh    = (__half*)p;
    cudaGetSymbolAddress(&p, g_wvh);   __half* wvh   = (__half*)p;
    cudaGetSymbolAddress(&p, g_wffh);  __half* wffh  = (__half*)p;
    cudaGetSymbolAddress(&p, g_wouth); __half* wouth = (__half*)p;
    cudaGetSymbolAddress(&p, g_vth);   __half* vth   = (__half*)p;
    cudaGetSymbolAddress(&p, g_attnh); __half* attnh = (__half*)p;
    cudaGetSymbolAddress(&p, g_ctxh);  __half* ctxh  = (__half*)p;
    cudaGetSymbolAddress(&p, g_ffh);   __half* ffh   = (__half*)p;

    cudaFuncSetAttribute(gemm_tc<0>, cudaFuncAttributeMaxDynamicSharedMemorySize, SMEM_GEMM);
    cudaFuncSetAttribute(gemm_tc<1>, cudaFuncAttributeMaxDynamicSharedMemorySize, SMEM_GEMM);

    const int M = NB * SQ;  // 8192

    // 0) operand prep (division-free exact grids)
    split_cvt_x<<<dim3(DIN / 4 / 256, M), 256>>>(x, xs, xh, DIN);
    transpose_split<<<dim3(DH / 64, DIN / 64, 1), 256>>>(Wq, wqs, DIN, DH);
    transpose_split<<<dim3(DH / 64, DIN / 64, 1), 256>>>(Wk, wks, DIN, DH);
    transpose_h<<<dim3(DH / 64, DIN / 64, 1), 256>>>(Wv, wvh, DIN, DH, 0, 0);
    transpose_h<<<dim3(DFF / 64, DH / 64, 1), 256>>>(Wff, wffh, DH, DFF, 0, 0);
    transpose_h<<<dim3(DH / 64, DFF / 64, 1), 256>>>(Wout, wouth, DFF, DH, 0, 0);
    cache_copy<<<dim3(PAST * DH / 4 / 256, NB), 256>>>(kc, vc, kout, vout);

    // 1) projections: q,k bf16x3 (K'=6144); v plain fp16 (K=2048)
    gemm_tc<0><<<dim3(DH / 128, M / 128, 1), 128, SMEM_GEMM>>>(
        (const uint16_t*)xs, (const uint16_t*)wqs, bq, nullptr, qs, nullptr,
        DH, 3 * DIN, 0, 0, M, 0);
    gemm_tc<0><<<dim3(DH / 128, SQ / 128, NB), 128, SMEM_GEMM>>>(
        (const uint16_t*)xs, (const uint16_t*)wks, bk, kout, nullptr, nullptr,
        DH, 3 * DIN, (long long)SQ * 3 * DIN, 0, KVLEN, PAST);
    gemm_tc<1><<<dim3(DH / 128, SQ / 128, NB), 128, SMEM_GEMM>>>(
        (const uint16_t*)xh, (const uint16_t*)wvh, bv, vout, nullptr, nullptr,
        DH, DIN, (long long)SQ * DIN, 0, KVLEN, PAST);

    // 2) K cache -> bf16 B-split; V cache -> fp16 transpose
    split_rows_b<<<dim3(DH / 4 / 256, NB * KVLEN), 256>>>(kout, ks, DH);
    transpose_h<<<dim3(DH / 64, KVLEN / 64, NB), 256>>>(
        vout, vth, KVLEN, DH, (long long)KVLEN * DH, (long long)DH * KVLEN);

    // 3) scores = q' @ k'^T  (bf16x3, K'=6144)
    gemm_tc<0><<<dim3(KVLEN / 128, SQ / 128, NB), 128, SMEM_GEMM>>>(
        (const uint16_t*)qs, (const uint16_t*)ks, nullptr, scores, nullptr, nullptr,
        KVLEN, 3 * DH, (long long)SQ * 3 * DH, (long long)KVLEN * 3 * DH, SQ, 0);

    // 4) softmax over query axis -> fp16 attn
    softmax_h<<<dim3(KVLEN / 64, NB), 256>>>(scores, attnh);

    // 5) ctx = attn @ v  (fp16, K=4096) -> fp16 ctx
    gemm_tc<1><<<dim3(DH / 128, SQ / 128, NB), 128, SMEM_GEMM>>>(
        (const uint16_t*)attnh, (const uint16_t*)vth, nullptr, nullptr, nullptr, ctxh,
        DH, KVLEN, (long long)SQ * KVLEN, (long long)DH * KVLEN, SQ, 0);

    // 6) FFN (fp16): ff = ctx @ Wff^T + bff ; out = ff @ Wout^T + bout
    gemm_tc<1><<<dim3(DFF / 128, M / 128, 1), 128, SMEM_GEMM>>>(
        (const uint16_t*)ctxh, (const uint16_t*)wffh, bff, nullptr, nullptr, ffh,
        DFF, DH, 0, 0, M, 0);
    gemm_tc<1><<<dim3(DH / 128, M / 128, 1), 128, SMEM_GEMM>>>(
        (const uint16_t*)ffh, (const uint16_t*)wouth, bout, out, nullptr, nullptr,
        DH, DFF, 0, 0, M, 0);
}